// round 1
// baseline (speedup 1.0000x reference)
#include <cuda_runtime.h>

// ---------------------------------------------------------------------------
// ModelBasedNet: MLP -> softmax risk budgets -> per-sample risk-budget QP via
// damped Newton (20 iters), each iteration doing a 200x200 SPD Cholesky solve
// entirely in shared memory. One CTA per sample; 2 CTAs/SM.
// Outputs: z (512x200) then b (512x200) into d_out.
// ---------------------------------------------------------------------------

constexpr int BATCH = 512;
constexpr int NFE   = 128;   // features
constexpr int NAS   = 200;   // assets
constexpr int HID   = 256;   // hidden
constexpr int NIT   = 20;    // Newton iterations (match reference exactly)
constexpr int KB    = 8;     // Cholesky panel width (200 % 8 == 0)
constexpr float ALPHA_LR = 0.01f;
constexpr float BMIN     = 1e-4f;

// packed lower triangle, each row i padded to multiple of 4 floats
// total = sum_{i=0..199} ((i+4)&~3) = 20400
constexpr int NP4 = 20400;

// shared layout (floats): P[NP4], y[200], b[200], z[200], dy[200], invd[200],
//                         red[256], pinv2[8], rof[201] (ints)
constexpr int SMEM_FLOATS = NP4 + 5 * NAS + 256 + KB;
constexpr int SMEM_BYTES  = SMEM_FLOATS * 4 + (NAS + 1) * 4;

__device__ float g_bc[BATCH * NAS];   // clamped+renormalized budgets

// ---------------------------------------------------------------------------
// Kernel 1: h = LeakyReLU(x W1^T + b1); logits = h W2^T + b2; softmax -> b;
//           bc = renorm(clip(b, BMIN)).  Writes b to out, bc to g_bc.
// ---------------------------------------------------------------------------
__global__ __launch_bounds__(256) void mlp_kernel(
    const float* __restrict__ x,
    const float* __restrict__ W1, const float* __restrict__ b1,
    const float* __restrict__ W2, const float* __restrict__ b2,
    float* __restrict__ out)
{
    __shared__ float xs[NFE];
    __shared__ float hs[HID];
    __shared__ float ls[NAS];
    __shared__ float red[256];

    const int s    = blockIdx.x;
    const int tid  = threadIdx.x;
    const int warp = tid >> 5;
    const int lane = tid & 31;

    if (tid < NFE) xs[tid] = x[s * NFE + tid];
    __syncthreads();

    // hidden layer: each warp computes 32 outputs; coalesced float4 W1 reads
    for (int r = 0; r < 32; ++r) {
        int j = warp * 32 + r;
        const float4* w = (const float4*)(W1 + (size_t)j * NFE);
        float4 a = w[lane];
        int k = lane * 4;
        float acc = a.x * xs[k] + a.y * xs[k + 1] + a.z * xs[k + 2] + a.w * xs[k + 3];
        #pragma unroll
        for (int o = 16; o > 0; o >>= 1) acc += __shfl_down_sync(0xffffffffu, acc, o);
        if (lane == 0) {
            float v = acc + b1[j];
            hs[j] = (v >= 0.f) ? v : ALPHA_LR * v;
        }
    }
    __syncthreads();

    // logits: 200 outputs, 25 per warp
    for (int r = 0; r < 25; ++r) {
        int j = warp * 25 + r;
        const float4* w = (const float4*)(W2 + (size_t)j * HID);
        float acc = 0.f;
        #pragma unroll
        for (int c = 0; c < 2; ++c) {
            float4 a = w[lane * 2 + c];
            int k = (lane * 2 + c) * 4;
            acc += a.x * hs[k] + a.y * hs[k + 1] + a.z * hs[k + 2] + a.w * hs[k + 3];
        }
        #pragma unroll
        for (int o = 16; o > 0; o >>= 1) acc += __shfl_down_sync(0xffffffffu, acc, o);
        if (lane == 0) ls[j] = acc + b2[j];
    }
    __syncthreads();

    // softmax over 200
    red[tid] = (tid < NAS) ? ls[tid] : -3.0e38f;
    __syncthreads();
    for (int o = 128; o > 0; o >>= 1) {
        if (tid < o) red[tid] = fmaxf(red[tid], red[tid + o]);
        __syncthreads();
    }
    float m = red[0];
    __syncthreads();

    float e = (tid < NAS) ? expf(ls[tid] - m) : 0.f;
    red[tid] = e;
    __syncthreads();
    for (int o = 128; o > 0; o >>= 1) {
        if (tid < o) red[tid] += red[tid + o];
        __syncthreads();
    }
    float denom = red[0];
    __syncthreads();

    float bb = e / denom;                      // raw softmax budget
    if (tid < NAS) out[(size_t)BATCH * NAS + (size_t)s * NAS + tid] = bb;

    float bcv = fmaxf(bb, BMIN);
    red[tid] = (tid < NAS) ? bcv : 0.f;
    __syncthreads();
    for (int o = 128; o > 0; o >>= 1) {
        if (tid < o) red[tid] += red[tid + o];
        __syncthreads();
    }
    float s2 = red[0];
    __syncthreads();
    if (tid < NAS) g_bc[s * NAS + tid] = bcv / s2;
}

// ---------------------------------------------------------------------------
// Kernel 2: per-sample damped Newton on 0.5 y'Sy - b'log(y).
// Packed-lower-triangle Cholesky (unscaled columns + 1/d), blocked KB=8.
// ---------------------------------------------------------------------------
__global__ __launch_bounds__(256) void newton_kernel(
    const float* __restrict__ Sigma, float* __restrict__ out_z)
{
    extern __shared__ float sm[];
    float* P     = sm;                 // NP4
    float* yv    = P + NP4;            // NAS
    float* bv    = yv + NAS;           // NAS
    float* zv    = bv + NAS;           // NAS  (rhs / residual)
    float* dyv   = zv + NAS;           // NAS
    float* invd  = dyv + NAS;          // NAS  (1/d_k)
    float* red   = invd + NAS;         // 256
    float* pinv2 = red + 256;          // KB
    int*   rof   = (int*)(pinv2 + KB); // NAS+1 padded row offsets

    const int s   = blockIdx.x;
    const int tid = threadIdx.x;
    const float* S = Sigma + (size_t)s * NAS * NAS;

    if (tid == 0) {
        int o = 0;
        for (int i = 0; i < NAS; ++i) { rof[i] = o; o += (i + 4) & ~3; }
        rof[NAS] = o;
    }
    if (tid < NAS) bv[tid] = g_bc[s * NAS + tid];
    __syncthreads();

    const int roi_t = (tid < NAS) ? (tid < NAS ? rof[tid] : 0) : 0;

    // --- load lower triangle of S into packed shared (coalesced per row) ---
    auto load_S = [&]() {
        int ro = 0;
        for (int i = 0; i < NAS; ++i) {
            if (tid <= i) P[ro + tid] = S[(size_t)i * NAS + tid];
            ro += (i + 4) & ~3;
        }
    };

    // --- symmetric matvec from packed P: returns (P v)_tid ---
    auto symv = [&](const float* v) -> float {
        float acc = 0.f;
        if (tid < NAS) {
            int roi = roi_t;
            for (int j = 0; j <= tid; ++j) acc += P[roi + j] * v[j];
            for (int j = tid + 1; j < NAS; ++j) acc += P[rof[j] + tid] * v[j];
        }
        return acc;
    };

    // --- y0 = b / sqrt(b'Sb) ---
    load_S();
    __syncthreads();
    {
        float sb = symv(bv);
        red[tid] = (tid < NAS) ? bv[tid] * sb : 0.f;
        __syncthreads();
        for (int o = 128; o > 0; o >>= 1) {
            if (tid < o) red[tid] += red[tid + o];
            __syncthreads();
        }
        float Q = red[0];
        __syncthreads();
        if (tid < NAS) yv[tid] = bv[tid] * rsqrtf(Q);
        __syncthreads();
    }

    // --- Newton iterations ---
    for (int it = 0; it < NIT; ++it) {
        if (it > 0) { load_S(); __syncthreads(); }

        // rhs = -g = b/y - S y   (uses pristine P)
        float sy = symv(yv);
        float rhs = 0.f;
        if (tid < NAS) rhs = bv[tid] / yv[tid] - sy;
        __syncthreads();                 // all symv reads done before diag write
        if (tid < NAS) {
            zv[tid] = rhs;
            float yy = yv[tid];
            P[roi_t + tid] += bv[tid] / (yy * yy);   // Hm = S + diag(b/y^2)
        }

        // ---- blocked Cholesky (unscaled columns; invd[k] = 1/d_k) ----
        for (int k0 = 0; k0 < NAS; k0 += KB) {
            // panel factorization (columns k0..k0+7)
            for (int k = k0; k < k0 + KB; ++k) {
                __syncthreads();
                float d  = P[rof[k] + k];
                float i2 = 1.0f / d;
                if (tid == 0) { invd[k] = i2; pinv2[k - k0] = i2; }
                int i = k + 1 + tid;
                if (i < NAS) {
                    int roi = rof[i];
                    float f = P[roi + k] * i2;
                    int je = (i < k0 + KB - 1) ? i : (k0 + KB - 1);
                    for (int j = k + 1; j <= je; ++j)
                        P[roi + j] -= f * P[rof[j] + k];
                }
            }
            __syncthreads();
            // block trailing update: A[i][j] -= sum_c C[i][c]*C[j][c]/d_c
            int i = k0 + KB + tid;
            if (i < NAS) {
                int roi = rof[i];
                float4 ca = *(const float4*)&P[roi + k0];
                float4 cb = *(const float4*)&P[roi + k0 + 4];
                float4 pa = *(const float4*)&pinv2[0];
                float4 pb = *(const float4*)&pinv2[4];
                float f0 = ca.x * pa.x, f1 = ca.y * pa.y, f2 = ca.z * pa.z, f3 = ca.w * pa.w;
                float f4 = cb.x * pb.x, f5 = cb.y * pb.y, f6 = cb.z * pb.z, f7 = cb.w * pb.w;
                int rj = rof[k0 + KB];
                #pragma unroll 2
                for (int j = k0 + KB; j <= i; ++j) {
                    float4 a  = *(const float4*)&P[rj + k0];
                    float4 b4 = *(const float4*)&P[rj + k0 + 4];
                    float vv = P[roi + j];
                    vv -= f0 * a.x;  vv -= f1 * a.y;  vv -= f2 * a.z;  vv -= f3 * a.w;
                    vv -= f4 * b4.x; vv -= f5 * b4.y; vv -= f6 * b4.z; vv -= f7 * b4.w;
                    P[roi + j] = vv;
                    rj += (j + 4) & ~3;
                }
            }
        }

        // ---- forward sweep: L w = rhs (zv becomes v = s.*w) ----
        for (int j = 0; j < NAS - 1; ++j) {
            __syncthreads();
            float t = zv[j] * invd[j];
            int i = j + 1 + tid;
            if (i < NAS) zv[i] -= P[rof[i] + j] * t;
        }
        // ---- backward sweep: L^T dy = w ----
        for (int i = NAS - 1; i > 0; --i) {
            __syncthreads();
            float di = zv[i] * invd[i];
            if (tid == 0) dyv[i] = di;
            if (tid < i) zv[tid] -= P[rof[i] + tid] * di;
        }
        __syncthreads();
        if (tid == 0) dyv[0] = zv[0] * invd[0];
        __syncthreads();

        // ---- damped update (exact reference semantics) ----
        float dy = (tid < NAS) ? dyv[tid] : 1.0f;
        float yi = (tid < NAS) ? yv[tid] : 1.0f;
        float ratio = (dy < 0.f) ? (-yi / dy) : 1e30f;
        red[tid] = (tid < NAS) ? ratio : 1e30f;
        __syncthreads();
        for (int o = 128; o > 0; o >>= 1) {
            if (tid < o) red[tid] = fminf(red[tid], red[tid + o]);
            __syncthreads();
        }
        float t = fminf(1.0f, 0.9f * red[0]);
        __syncthreads();
        if (tid < NAS) yv[tid] = fmaxf(yi + t * dy, 1e-12f);
        __syncthreads();
    }

    // z = y / sum(y)
    float yy = (tid < NAS) ? yv[tid] : 0.f;
    red[tid] = yy;
    __syncthreads();
    for (int o = 128; o > 0; o >>= 1) {
        if (tid < o) red[tid] += red[tid + o];
        __syncthreads();
    }
    float ssum = red[0];
    if (tid < NAS) out_z[(size_t)s * NAS + tid] = yy / ssum;
}

// ---------------------------------------------------------------------------
extern "C" void kernel_launch(void* const* d_in, const int* in_sizes, int n_in,
                              void* d_out, int out_size)
{
    const float* x     = (const float*)d_in[0];
    const float* Sigma = (const float*)d_in[1];
    const float* W1    = (const float*)d_in[2];
    const float* b1    = (const float*)d_in[3];
    const float* W2    = (const float*)d_in[4];
    const float* b2    = (const float*)d_in[5];
    float* out = (float*)d_out;

    cudaFuncSetAttribute(newton_kernel,
                         cudaFuncAttributeMaxDynamicSharedMemorySize, SMEM_BYTES);

    mlp_kernel<<<BATCH, 256>>>(x, W1, b1, W2, b2, out);
    newton_kernel<<<BATCH, 256, SMEM_BYTES>>>(Sigma, out);
}

// round 2
// speedup vs baseline: 1.3521x; 1.3521x over previous
#include <cuda_runtime.h>

// ---------------------------------------------------------------------------
// ModelBasedNet: MLP -> softmax risk budgets -> per-sample risk-budget QP via
// damped Newton (20 iters) with a 200x200 SPD Cholesky solve in shared memory.
// Round 2: odd row padding (kills 4-way bank conflicts), 512 threads/CTA with
// j-split trailing update, compact broadcast panel buffer, blocked sweeps.
// Outputs: z (512x200) then b (512x200) into d_out.
// ---------------------------------------------------------------------------

constexpr int BATCH = 512;
constexpr int NFE   = 128;
constexpr int NAS   = 200;
constexpr int HID   = 256;
constexpr int NIT   = 20;    // match reference exactly
constexpr int KB    = 8;     // Cholesky panel width
constexpr float ALPHA_LR = 0.01f;
constexpr float BMIN     = 1e-4f;

// packed lower triangle, row i padded to odd length (i+1)|1  -> bank spread
// total = 20100 + 100 = 20200 floats
constexpr int NPAD   = 20200;
constexpr int WPROWS = NAS - KB;   // 192 rows max in compact panel buffer

constexpr int SMEM_FLOATS = NPAD + WPROWS * KB + 5 * NAS + 512 + KB;
constexpr int SMEM_BYTES  = SMEM_FLOATS * 4 + (NAS + 1) * 4;

__device__ float g_bc[BATCH * NAS];   // clamped+renormalized budgets

// ---------------------------------------------------------------------------
// Kernel 1: MLP + softmax + clip/renorm. Writes b to out, bc to g_bc.
// ---------------------------------------------------------------------------
__global__ __launch_bounds__(256) void mlp_kernel(
    const float* __restrict__ x,
    const float* __restrict__ W1, const float* __restrict__ b1,
    const float* __restrict__ W2, const float* __restrict__ b2,
    float* __restrict__ out)
{
    __shared__ float xs[NFE];
    __shared__ float hs[HID];
    __shared__ float ls[NAS];
    __shared__ float red[256];

    const int s    = blockIdx.x;
    const int tid  = threadIdx.x;
    const int warp = tid >> 5;
    const int lane = tid & 31;

    if (tid < NFE) xs[tid] = x[s * NFE + tid];
    __syncthreads();

    for (int r = 0; r < 32; ++r) {
        int j = warp * 32 + r;
        const float4* w = (const float4*)(W1 + (size_t)j * NFE);
        float4 a = w[lane];
        int k = lane * 4;
        float acc = a.x * xs[k] + a.y * xs[k + 1] + a.z * xs[k + 2] + a.w * xs[k + 3];
        #pragma unroll
        for (int o = 16; o > 0; o >>= 1) acc += __shfl_down_sync(0xffffffffu, acc, o);
        if (lane == 0) {
            float v = acc + b1[j];
            hs[j] = (v >= 0.f) ? v : ALPHA_LR * v;
        }
    }
    __syncthreads();

    for (int r = 0; r < 25; ++r) {
        int j = warp * 25 + r;
        const float4* w = (const float4*)(W2 + (size_t)j * HID);
        float acc = 0.f;
        #pragma unroll
        for (int c = 0; c < 2; ++c) {
            float4 a = w[lane * 2 + c];
            int k = (lane * 2 + c) * 4;
            acc += a.x * hs[k] + a.y * hs[k + 1] + a.z * hs[k + 2] + a.w * hs[k + 3];
        }
        #pragma unroll
        for (int o = 16; o > 0; o >>= 1) acc += __shfl_down_sync(0xffffffffu, acc, o);
        if (lane == 0) ls[j] = acc + b2[j];
    }
    __syncthreads();

    red[tid] = (tid < NAS) ? ls[tid] : -3.0e38f;
    __syncthreads();
    for (int o = 128; o > 0; o >>= 1) {
        if (tid < o) red[tid] = fmaxf(red[tid], red[tid + o]);
        __syncthreads();
    }
    float m = red[0];
    __syncthreads();

    float e = (tid < NAS) ? expf(ls[tid] - m) : 0.f;
    red[tid] = e;
    __syncthreads();
    for (int o = 128; o > 0; o >>= 1) {
        if (tid < o) red[tid] += red[tid + o];
        __syncthreads();
    }
    float denom = red[0];
    __syncthreads();

    float bb = e / denom;
    if (tid < NAS) out[(size_t)BATCH * NAS + (size_t)s * NAS + tid] = bb;

    float bcv = fmaxf(bb, BMIN);
    red[tid] = (tid < NAS) ? bcv : 0.f;
    __syncthreads();
    for (int o = 128; o > 0; o >>= 1) {
        if (tid < o) red[tid] += red[tid + o];
        __syncthreads();
    }
    float s2 = red[0];
    __syncthreads();
    if (tid < NAS) g_bc[s * NAS + tid] = bcv / s2;
}

// ---------------------------------------------------------------------------
// Kernel 2: per-sample damped Newton. 512 threads (two halves of 256).
// ---------------------------------------------------------------------------
__global__ __launch_bounds__(512, 2) void newton_kernel(
    const float* __restrict__ Sigma, float* __restrict__ out_z)
{
    extern __shared__ float sm[];
    float* P    = sm;                    // NPAD
    float* Wp   = P + NPAD;              // WPROWS*KB (compact scaled-panel buf)
    float* yv   = Wp + WPROWS * KB;      // NAS
    float* bv   = yv + NAS;              // NAS
    float* zv   = bv + NAS;              // NAS
    float* dyv  = zv + NAS;              // NAS
    float* invd = dyv + NAS;             // NAS
    float* red  = invd + NAS;            // 512
    float* tb   = red + 512;             // KB
    int*   rof  = (int*)(tb + KB);       // NAS+1 row offsets (odd lengths)

    const int s    = blockIdx.x;
    const int tid  = threadIdx.x;
    const int half = tid >> 8;           // 0 or 1
    const int r    = tid & 255;
    const float* S = Sigma + (size_t)s * NAS * NAS;

    if (tid == 0) {
        int o = 0;
        for (int i = 0; i < NAS; ++i) { rof[i] = o; o += (i + 1) | 1; }
        rof[NAS] = o;
    }
    if (tid < NAS) bv[tid] = g_bc[s * NAS + tid];
    __syncthreads();

    // ---- load lower triangle of S (two rows per step, 512 threads) ----
    auto load_S = [&]() {
        #pragma unroll 1
        for (int i0 = 0; i0 < NAS; i0 += 2) {
            int i = i0 + half;
            if (r <= i) P[rof[i] + r] = S[(size_t)i * NAS + r];
        }
    };

    // ---- symmetric matvec, split: this thread sums j in [100*half,100*half+100) ----
    auto symv_part = [&](const float* v) -> float {
        float acc = 0.f;
        if (r < NAS) {
            int ro = rof[r];
            int j0 = half * 100;
            #pragma unroll 4
            for (int j = j0; j < j0 + 100; ++j) {
                int idx = (j <= r) ? (ro + j) : (rof[j] + r);
                acc += P[idx] * v[j];
            }
        }
        return acc;
    };

    // ---- y0 = b / sqrt(b'Sb) ----
    load_S();
    __syncthreads();
    {
        float sb = symv_part(bv);
        red[tid] = sb;
        __syncthreads();
        float q = (tid < NAS) ? bv[tid] * (red[tid] + red[tid + 256]) : 0.f;
        __syncthreads();
        red[tid] = q;
        __syncthreads();
        for (int o = 256; o > 0; o >>= 1) {
            if (tid < o) red[tid] += red[tid + o];
            __syncthreads();
        }
        float Q = red[0];
        __syncthreads();
        if (tid < NAS) yv[tid] = bv[tid] * rsqrtf(Q);
        __syncthreads();
    }

    // ---- Newton iterations ----
    for (int it = 0; it < NIT; ++it) {
        if (it > 0) { load_S(); __syncthreads(); }

        // rhs = b/y - S y ; Hm = S + diag(b/y^2)
        float sy = symv_part(yv);
        red[tid] = sy;
        __syncthreads();
        if (tid < NAS) {
            float syf = red[tid] + red[tid + 256];
            float yy  = yv[tid];
            zv[tid] = bv[tid] / yy - syf;
            P[rof[tid] + tid] += bv[tid] / (yy * yy);
        }

        // ---- blocked Cholesky, unscaled columns (invd[k] = 1/d_k) ----
        for (int k0 = 0; k0 < NAS; k0 += KB) {
            const int k1 = k0 + KB;
            // panel columns
            for (int k = k0; k < k1; ++k) {
                __syncthreads();
                float i2 = 1.0f / P[rof[k] + k];
                if (tid == 0) invd[k] = i2;
                int i = k + 1 + tid;
                if (i < NAS) {
                    int roi = rof[i];
                    float f = P[roi + k] * i2;
                    int je = (i < k1 - 1) ? i : (k1 - 1);
                    for (int j = k + 1; j <= je; ++j)
                        P[roi + j] -= f * P[rof[j] + k];
                }
            }
            __syncthreads();
            if (k1 >= NAS) break;

            // phase A: gather own panel row; lower half publishes compact copy
            const int m    = NAS - k1;
            const bool act = (r < m);
            const int irow = k1 + r;
            int roi = 0;
            float f[KB];
            if (act) {
                roi = rof[irow];
                #pragma unroll
                for (int c = 0; c < KB; ++c) f[c] = P[roi + k0 + c];
                if (half == 0) {
                    #pragma unroll
                    for (int c = 0; c < KB; ++c) Wp[r * KB + c] = f[c];
                }
                #pragma unroll
                for (int c = 0; c < KB; ++c) f[c] *= invd[k0 + c];
            }
            __syncthreads();

            // phase B: trailing update, j-range split between halves
            if (act) {
                int L   = irow - k1 + 1;
                int jlo = k1 + (half ? (L >> 1) : 0);
                int jhi = half ? (irow + 1) : (k1 + (L >> 1));
                int j   = jlo;
                for (; j + 1 < jhi; j += 2) {
                    const float* w0 = &Wp[(j - k1) * KB];
                    float4 a0 = *(const float4*)(w0);
                    float4 b0 = *(const float4*)(w0 + 4);
                    float4 a1 = *(const float4*)(w0 + 8);
                    float4 b1 = *(const float4*)(w0 + 12);
                    float v0 = P[roi + j];
                    float v1 = P[roi + j + 1];
                    float s0 = f[0] * a0.x, t0 = f[1] * a0.y;
                    s0 = fmaf(f[2], a0.z, s0); t0 = fmaf(f[3], a0.w, t0);
                    s0 = fmaf(f[4], b0.x, s0); t0 = fmaf(f[5], b0.y, t0);
                    s0 = fmaf(f[6], b0.z, s0); t0 = fmaf(f[7], b0.w, t0);
                    float s1 = f[0] * a1.x, t1 = f[1] * a1.y;
                    s1 = fmaf(f[2], a1.z, s1); t1 = fmaf(f[3], a1.w, t1);
                    s1 = fmaf(f[4], b1.x, s1); t1 = fmaf(f[5], b1.y, t1);
                    s1 = fmaf(f[6], b1.z, s1); t1 = fmaf(f[7], b1.w, t1);
                    P[roi + j]     = v0 - (s0 + t0);
                    P[roi + j + 1] = v1 - (s1 + t1);
                }
                if (j < jhi) {
                    const float* w0 = &Wp[(j - k1) * KB];
                    float4 a0 = *(const float4*)(w0);
                    float4 b0 = *(const float4*)(w0 + 4);
                    float v0 = P[roi + j];
                    float s0 = f[0] * a0.x, t0 = f[1] * a0.y;
                    s0 = fmaf(f[2], a0.z, s0); t0 = fmaf(f[3], a0.w, t0);
                    s0 = fmaf(f[4], b0.x, s0); t0 = fmaf(f[5], b0.y, t0);
                    s0 = fmaf(f[6], b0.z, s0); t0 = fmaf(f[7], b0.w, t0);
                    P[roi + j] = v0 - (s0 + t0);
                }
            }
        }

        // ---- blocked forward sweep: L w = rhs ----
        for (int k0 = 0; k0 < NAS; k0 += KB) {
            const int k1 = k0 + KB;
            __syncthreads();
            if (tid < 32) {
                for (int j = k0; j < k1; ++j) {
                    float t = zv[j] * invd[j];
                    int i = j + 1 + tid;
                    if (i < k1) zv[i] -= P[rof[i] + j] * t;
                    if (tid == 0) tb[j - k0] = t;
                    __syncwarp();
                }
            }
            __syncthreads();
            int i = k1 + tid;
            if (i < NAS) {
                int ro = rof[i];
                float acc = 0.f;
                #pragma unroll
                for (int c = 0; c < KB; ++c) acc = fmaf(P[ro + k0 + c], tb[c], acc);
                zv[i] -= acc;
            }
        }

        // ---- blocked backward sweep: L^T dy = w ----
        for (int k0 = NAS - KB; k0 >= 0; k0 -= KB) {
            const int k1 = k0 + KB;
            __syncthreads();
            if (tid < 32) {
                for (int i = k1 - 1; i >= k0; --i) {
                    float di = zv[i] * invd[i];
                    int t = k0 + tid;
                    if (t < i) zv[t] -= P[rof[i] + t] * di;
                    if (tid == 0) { dyv[i] = di; tb[i - k0] = di; }
                    __syncwarp();
                }
            }
            __syncthreads();
            if (tid < k0) {
                float acc = 0.f;
                #pragma unroll
                for (int c = 0; c < KB; ++c) acc = fmaf(P[rof[k0 + c] + tid], tb[c], acc);
                zv[tid] -= acc;
            }
        }
        __syncthreads();

        // ---- damped update (exact reference semantics) ----
        float ddy = (tid < NAS) ? dyv[tid] : 0.f;
        float yy  = (tid < NAS) ? yv[tid]  : 1.f;
        float ratio = (ddy < 0.f) ? (-yy / ddy) : 1e30f;
        red[tid] = (tid < NAS) ? ratio : 1e30f;
        __syncthreads();
        for (int o = 256; o > 0; o >>= 1) {
            if (tid < o) red[tid] = fminf(red[tid], red[tid + o]);
            __syncthreads();
        }
        float tstep = fminf(1.0f, 0.9f * red[0]);
        __syncthreads();
        if (tid < NAS) yv[tid] = fmaxf(yy + tstep * ddy, 1e-12f);
        __syncthreads();
    }

    // ---- z = y / sum(y) ----
    float yy = (tid < NAS) ? yv[tid] : 0.f;
    red[tid] = yy;
    __syncthreads();
    for (int o = 256; o > 0; o >>= 1) {
        if (tid < o) red[tid] += red[tid + o];
        __syncthreads();
    }
    float ssum = red[0];
    if (tid < NAS) out_z[(size_t)s * NAS + tid] = yy / ssum;
}

// ---------------------------------------------------------------------------
extern "C" void kernel_launch(void* const* d_in, const int* in_sizes, int n_in,
                              void* d_out, int out_size)
{
    const float* x     = (const float*)d_in[0];
    const float* Sigma = (const float*)d_in[1];
    const float* W1    = (const float*)d_in[2];
    const float* b1    = (const float*)d_in[3];
    const float* W2    = (const float*)d_in[4];
    const float* b2    = (const float*)d_in[5];
    float* out = (float*)d_out;

    cudaFuncSetAttribute(newton_kernel,
                         cudaFuncAttributeMaxDynamicSharedMemorySize, SMEM_BYTES);

    mlp_kernel<<<BATCH, 256>>>(x, W1, b1, W2, b2, out);
    newton_kernel<<<BATCH, 512, SMEM_BYTES>>>(Sigma, out);
}